// round 13
// baseline (speedup 1.0000x reference)
#include <cuda_runtime.h>

// Model_10582799417658: 127-step LSTM-VAE rollout.
// B=4096, D=64, H=256, GATES=1024, L=64, T=128 (127 scan steps).
//
// Round 13: 2 CTAs/SM decoupling. BT=16, NTH=256, 256 CTAs,
// __launch_bounds__(256,2). Same inner loop / per-thread tile as round 12;
// independent barriers + cp.async waits per CTA hide each other's stalls.
// 2-slot 32KB panel rings; mus/lvs/zs overlaid in slot0.

#define B_TOT   4096
#define T_STEPS 127
#define D_IN    64
#define HID     256
#define GATE    1024
#define LAT     64
#define BT      16
#define NTH     256
#define NCTA    (B_TOT / BT)   // 256
#define MS      20             // padded m-stride (floats)
#define PK      8              // phase-1 panel depth
#define NP1     40             // 320 / 8
#define PK2     32             // phase-2 panel depth
#define NP2     8              // 256 / 32
#define SLOTF   8192           // slot stride (floats, 32KB)

// ---- output layout ----
#define N_STATES ((unsigned long long)B_TOT * T_STEPS * D_IN)
#define N_GENS   ((unsigned long long)B_TOT * T_STEPS)
#define N_TOTS   ((unsigned long long)B_TOT * 128)
#define O_STATES 0ULL
#define O_GENS   (O_STATES + N_STATES)
#define O_ONOFF  (O_GENS + N_GENS)
#define O_TPRE   (O_ONOFF + N_GENS)
#define O_TPOST  (O_TPRE + N_TOTS)

typedef unsigned long long ull;

__device__ float g_wgv[HID];
__device__ float g_wov[HID];
__device__ float g_b2[2];
// Phase-1 weights, k-major + gate-interleaved (same as round 12):
//   g_Wt1[k*1024 +       jp*4 + g*2 + jj] = Wg[(g  )*256 + jp*2 + jj][k], g in {0,1}
//   g_Wt1[k*1024 + 512 + jp*4 + g*2 + jj] = Wg[(g+2)*256 + jp*2 + jj][k], g in {0,1}
// Phase-2: g_Wt2[k][r] = (r<64 ? Wmu[r][k] : Wvar[r-64][k])
__device__ float g_Wt1[320 * 1024];
__device__ float g_Wt2[256 * 128];

__device__ __forceinline__ ull pack2s(float a) {   // splat (a, a)
    ull r;
    asm("mov.b64 %0, {%1,%1};" : "=l"(r) : "r"(__float_as_uint(a)));
    return r;
}
__device__ __forceinline__ void fma2(ull &d, ull a, ull b) {
    asm("fma.rn.f32x2 %0, %1, %2, %0;" : "+l"(d) : "l"(a), "l"(b));
}
__device__ __forceinline__ float2 unpack2(ull v) {
    unsigned int lo, hi;
    asm("mov.b64 {%0,%1}, %2;" : "=r"(lo), "=r"(hi) : "l"(v));
    float2 f; f.x = __uint_as_float(lo); f.y = __uint_as_float(hi);
    return f;
}
__device__ __forceinline__ float sig_f(float x) {
    return 1.0f / (1.0f + __expf(-x));
}
__device__ __forceinline__ float tanh_f(float x) {
    return 1.0f - 2.0f / (__expf(2.0f * x) + 1.0f);
}
__device__ __forceinline__ void cpa16(unsigned int dst, const void* src) {
    asm volatile("cp.async.cg.shared.global [%0], [%1], 16;" :: "r"(dst), "l"(src));
}
__device__ __forceinline__ void cpa_commit() {
    asm volatile("cp.async.commit_group;");
}
__device__ __forceinline__ void cpa_wait0() {
    asm volatile("cp.async.wait_group 0;");
}

// Merged one-time prep: rank-1 head folds + k-major weight transposes.
__global__ void prep_all_kernel(const float* __restrict__ Wih, const float* __restrict__ Whh,
                                const float* __restrict__ Wmu, const float* __restrict__ Wvar,
                                const float* __restrict__ Wgen, const float* __restrict__ bgen,
                                const float* __restrict__ Won,  const float* __restrict__ bon,
                                const float* __restrict__ Wvelo, const float* __restrict__ bvelo,
                                const float* __restrict__ Wsw,  const float* __restrict__ bsw) {
    const int stride = gridDim.x * blockDim.x;
    const int idx = blockIdx.x * blockDim.x + threadIdx.x;

    if (blockIdx.x == 0 && threadIdx.x < HID) {
        int k = threadIdx.x;
        float s1 = 0.f, s2 = 0.f;
        #pragma unroll 4
        for (int l = 0; l < LAT; ++l) {
            s1 += Wgen[l] * Wvelo[l * HID + k];
            s2 += Won[l]  * Wsw[l * HID + k];
        }
        g_wgv[k] = s1;
        g_wov[k] = s2;
        if (k == 0) {
            float b1 = bgen[0], b2 = bon[0];
            for (int l = 0; l < LAT; ++l) {
                b1 += Wgen[l] * bvelo[l];
                b2 += Won[l]  * bsw[l];
            }
            g_b2[0] = b1; g_b2[1] = b2;
        }
    }

    for (int i = idx; i < 320 * 1024; i += stride) {
        int k = i >> 10, d = i & 1023;
        int half = d >> 9, dd = d & 511;
        int jp = dd >> 2, q = dd & 3;
        int g = half * 2 + (q >> 1), jj = q & 1;
        int grow = g * 256 + jp * 2 + jj;
        g_Wt1[i] = (k < 64) ? Wih[grow * D_IN + k] : Whh[grow * HID + (k - 64)];
    }
    for (int i = idx; i < 256 * 128; i += stride) {
        int k = i >> 7, r = i & 127;
        g_Wt2[i] = (r < 64) ? Wmu[r * HID + k] : Wvar[(r - 64) * HID + k];
    }
}

// SMEM float offsets
#define SM_XS    0          // [64][MS]  = 1280
#define SM_HS    1280       // [256][MS] = 5120
#define SM_BSUM  6400       // 1024
#define SM_WGV   7424       // 256
#define SM_WOV   7680       // 256
#define SM_BMU   7936       // 64
#define SM_BVAR  8000       // 64
#define SM_BNX   8064       // 64
#define SM_WNT   8128       // 4096
#define SM_ABUF  12224      // 16
#define SM_WB    12240      // 2 slots x 8192
#define SM_TOTF  (SM_WB + 2 * SLOTF)   // 28624 floats = 114,496 B

__global__ void __launch_bounds__(NTH, 2)
model_kernel(const float* __restrict__ data, const float* __restrict__ locs,
             const float* __restrict__ bih,  const float* __restrict__ bhh,
             const float* __restrict__ bmu,  const float* __restrict__ bvar,
             const float* __restrict__ Wnext, const float* __restrict__ bnext,
             const float* __restrict__ Wloc, const float* __restrict__ bloc,
             const float* __restrict__ eps,  float* __restrict__ out) {
    extern __shared__ float sm[];
    float* xs     = sm + SM_XS;
    float* hs     = sm + SM_HS;
    float* bsum   = sm + SM_BSUM;
    float* wgv    = sm + SM_WGV;
    float* wov    = sm + SM_WOV;
    float* bmu_s  = sm + SM_BMU;
    float* bvar_s = sm + SM_BVAR;
    float* bnx_s  = sm + SM_BNX;
    float* wnT    = sm + SM_WNT;
    float* abuf   = sm + SM_ABUF;
    float* wbA    = sm + SM_WB;
    float* mus    = wbA;              // [64][MS] overlay in slot0 (after 2a)
    float* lvs    = wbA + 1280;       // [64][MS]
    float* zs     = wbA + 2560;       // [64][MS] (phase 2b/3 only)

    const unsigned int wb_u32 =
        (unsigned int)__cvta_generic_to_shared(wbA);

    const int tid   = threadIdx.x;
    const int bBase = blockIdx.x * BT;
    // phase-1 tile: 2 m-tiles of 8 rows x 128 hidden-pairs (x4 gates)
    const int m0A  = (tid & 1) * 8;
    const int jp   = tid >> 1;           // 0..127
    const int jt2A = jp * 2;
    const int wrp = tid >> 5, lane = tid & 31;   // wrp 0..7
    // phase-2a tile: 4 m-tiles of 4 x 64 row-pairs
    const int m08 = (tid & 3) * 4;
    const int jq2 = (tid >> 2) * 2;      // 0..126

    // ---------------- init ----------------
    for (int i = tid; i < D_IN * BT; i += NTH) {
        int k = i / BT, m = i % BT;
        xs[k * MS + m] = data[(size_t)(bBase + m) * (128 * D_IN) + k];
    }
    for (int i = tid; i < HID * BT; i += NTH) {
        int j = i / BT, m = i % BT;
        int b = bBase + m;
        hs[j * MS + m] = locs[b * 2] * Wloc[j * 2] + locs[b * 2 + 1] * Wloc[j * 2 + 1] + bloc[j];
    }
    for (int i = tid; i < GATE; i += NTH) bsum[i] = bih[i] + bhh[i];
    for (int i = tid; i < HID; i += NTH) { wgv[i] = g_wgv[i]; wov[i] = g_wov[i]; }
    for (int i = tid; i < LAT; i += NTH) { bmu_s[i] = bmu[i]; bvar_s[i] = bvar[i]; }
    for (int i = tid; i < D_IN; i += NTH) bnx_s[i] = bnext[i];
    for (int i = tid; i < LAT * D_IN; i += NTH) {   // wnT[l][c] = Wnext[c][l]
        int l = i >> 6, c = i & 63;
        wnT[i] = Wnext[c * LAT + l];
    }
    if (tid < BT) {
        out[O_TPRE  + (size_t)(bBase + tid) * 128] = 0.f;
        out[O_TPOST + (size_t)(bBase + tid) * 128] = 0.f;
    }
    const float bgv = g_b2[0], bov = g_b2[1];

    // c state in registers: thread owns cols (jt2A, jt2A+1) x rows m0A..m0A+7
    float c_reg[16];
    #pragma unroll
    for (int i = 0; i < 16; ++i) c_reg[i] = 0.f;
    __syncthreads();

    // panel issue helpers (cp.async, 16B granules)
    auto issue1 = [&](int p, int slot) {   // 8192 floats = 8 x 256 float4
        const float4* src = ((const float4*)g_Wt1) + (size_t)p * 2048 + tid;
        unsigned int dst = wb_u32 + (unsigned int)slot * (SLOTF * 4u) + tid * 16u;
        #pragma unroll
        for (int i = 0; i < 8; ++i)
            cpa16(dst + (unsigned int)i * 4096u, src + i * 256);
    };
    auto issue2 = [&](int p, int slot) {   // 4096 floats = 4 x 256 float4
        const float4* src = ((const float4*)g_Wt2) + (size_t)p * 1024 + tid;
        unsigned int dst = wb_u32 + (unsigned int)slot * (SLOTF * 4u) + tid * 16u;
        #pragma unroll
        for (int i = 0; i < 4; ++i)
            cpa16(dst + (unsigned int)i * 4096u, src + i * 256);
    };

    for (int t = 0; t < T_STEPS; ++t) {
        // prefetch eps for phase 2b (2 rows per warp)
        float ea[2], eb[2];
        {
            const int mr = wrp * 2;
            const float* ep = eps + ((size_t)t * B_TOT + bBase + mr) * LAT;
            ea[0] = __ldg(ep + lane);        eb[0] = __ldg(ep + lane + 32);
            ea[1] = __ldg(ep + LAT + lane);  eb[1] = __ldg(ep + LAT + lane + 32);
        }

        // ======== Phase 1: gates = x@Wih^T + h@Whh^T, LSTM update ========
        {
            issue1(0, 0); cpa_commit();

            ull acc[32];
            #pragma unroll
            for (int i = 0; i < 32; ++i) acc[i] = 0ULL;

            for (int p = 0; p < NP1; ++p) {
                cpa_wait0();         // panel p arrived
                __syncthreads();     // visible to all; panel p-1 fully consumed
                if (p + 1 < NP1) { issue1(p + 1, (p + 1) & 1); cpa_commit(); }
                const float* wc = wbA + (p & 1) * SLOTF;
                const float* Ab = (p < 8) ? (xs + p * PK * MS)
                                          : (hs + (p * PK - 64) * MS);
                #pragma unroll
                for (int kk = 0; kk < PK; ++kk) {
                    float4 a0 = *(const float4*)(Ab + kk * MS + m0A);
                    float4 a1 = *(const float4*)(Ab + kk * MS + m0A + 4);
                    const float* wr = wc + kk * 1024 + jp * 4;
                    ulonglong2 wA = *(const ulonglong2*)(wr);        // g0, g1
                    ulonglong2 wB = *(const ulonglong2*)(wr + 512);  // g2, g3
                    ull w0 = wA.x, w1 = wA.y, w2 = wB.x, w3 = wB.y;
                    #pragma unroll
                    for (int m = 0; m < 4; ++m) {
                        ull am = pack2s((&a0.x)[m]);
                        fma2(acc[m * 4 + 0], am, w0);
                        fma2(acc[m * 4 + 1], am, w1);
                        fma2(acc[m * 4 + 2], am, w2);
                        fma2(acc[m * 4 + 3], am, w3);
                    }
                    #pragma unroll
                    for (int m = 0; m < 4; ++m) {
                        ull am = pack2s((&a1.x)[m]);
                        fma2(acc[(m + 4) * 4 + 0], am, w0);
                        fma2(acc[(m + 4) * 4 + 1], am, w1);
                        fma2(acc[(m + 4) * 4 + 2], am, w2);
                        fma2(acc[(m + 4) * 4 + 3], am, w3);
                    }
                }
            }
            __syncthreads();         // all warps done reading hs/panels

            // prefetch phase-2a panel 0 into slot0 (overlaps epilogue MUFUs;
            // slot0's panel 38 long consumed)
            issue2(0, 0); cpa_commit();

            // epilogue: bias + LSTM nonlinearity; c in regs, h in place
            const int hj0 = jt2A, hj1 = jt2A + 1;
            const float bi0 = bsum[hj0],       bi1 = bsum[hj1];
            const float bf0 = bsum[256 + hj0], bf1 = bsum[256 + hj1];
            const float bg0 = bsum[512 + hj0], bg1 = bsum[512 + hj1];
            const float bo0 = bsum[768 + hj0], bo1 = bsum[768 + hj1];
            #pragma unroll
            for (int m = 0; m < 8; ++m) {
                const int mm = m0A + m;
                float2 vi = unpack2(acc[m * 4 + 0]);
                float2 vf = unpack2(acc[m * 4 + 1]);
                float2 vg = unpack2(acc[m * 4 + 2]);
                float2 vo = unpack2(acc[m * 4 + 3]);
                {
                    float iv = sig_f(vi.x + bi0), fv = sig_f(vf.x + bf0);
                    float gv = tanh_f(vg.x + bg0), ov = sig_f(vo.x + bo0);
                    float c = fv * c_reg[m * 2 + 0] + iv * gv;
                    c_reg[m * 2 + 0] = c;
                    hs[hj0 * MS + mm] = ov * tanh_f(c);
                }
                {
                    float iv = sig_f(vi.y + bi1), fv = sig_f(vf.y + bf1);
                    float gv = tanh_f(vg.y + bg1), ov = sig_f(vo.y + bo1);
                    float c = fv * c_reg[m * 2 + 1] + iv * gv;
                    c_reg[m * 2 + 1] = c;
                    hs[hj1 * MS + mm] = ov * tanh_f(c);
                }
            }
        }

        // ======== Phase 2a: [mu;logvar] = h @ [Wmu;Wvar]^T ========
        {
            ull acc2[4] = {0ULL, 0ULL, 0ULL, 0ULL};

            for (int p = 0; p < NP2; ++p) {
                cpa_wait0();
                __syncthreads();     // also orders phase-1 hs epilogue writes
                if (p + 1 < NP2) { issue2(p + 1, (p + 1) & 1); cpa_commit(); }
                const float* wc = wbA + (p & 1) * SLOTF;
                const int k0 = p * PK2;
                #pragma unroll
                for (int kk = 0; kk < PK2; ++kk) {
                    float4 a = *(const float4*)(hs + (k0 + kk) * MS + m08);
                    ull w = *(const ull*)(wc + kk * 128 + jq2);
                    fma2(acc2[0], pack2s(a.x), w);
                    fma2(acc2[1], pack2s(a.y), w);
                    fma2(acc2[2], pack2s(a.z), w);
                    fma2(acc2[3], pack2s(a.w), w);
                }
            }
            __syncthreads();         // all warps done with panel slots

            // epilogue: row pair (jq2, jq2+1) for 4 m rows -> mus/lvs (slot0)
            if (jq2 < 64) {
                const float b0 = bmu_s[jq2], b1 = bmu_s[jq2 + 1];
                #pragma unroll
                for (int m = 0; m < 4; ++m) {
                    float2 v = unpack2(acc2[m]);
                    mus[jq2 * MS + m08 + m]       = v.x + b0;
                    mus[(jq2 + 1) * MS + m08 + m] = v.y + b1;
                }
            } else {
                const int l0 = jq2 - 64;
                const float b0 = bvar_s[l0], b1 = bvar_s[l0 + 1];
                #pragma unroll
                for (int m = 0; m < 4; ++m) {
                    float2 v = unpack2(acc2[m]);
                    lvs[l0 * MS + m08 + m]       = v.x + b0;
                    lvs[(l0 + 1) * MS + m08 + m] = v.y + b1;
                }
            }
        }
        __syncthreads();

        // ======== Phase 2b: gen/on + reparameterized z ========
        #pragma unroll
        for (int r = 0; r < 2; ++r) {
            const int m = wrp * 2 + r;
            const int b = bBase + m;
            float gp = 0.f, op = 0.f;
            #pragma unroll
            for (int i2 = 0; i2 < 8; ++i2) {
                int k = lane + 32 * i2;
                float hv = hs[k * MS + m];
                gp = fmaf(hv, wgv[k], gp);
                op = fmaf(hv, wov[k], op);
            }
            #pragma unroll
            for (int s2 = 16; s2 > 0; s2 >>= 1) {
                gp += __shfl_xor_sync(0xffffffffu, gp, s2);
                op += __shfl_xor_sync(0xffffffffu, op, s2);
            }
            if (lane == 0) {
                float gen = fmaxf(gp + bgv, 0.f);
                float on  = (op + bov) > 0.f ? 1.f : 0.f;
                abuf[m] = gen * on;
                out[O_GENS  + (size_t)b * T_STEPS + t] = gen;
                out[O_ONOFF + (size_t)b * T_STEPS + t] = on;
            }
            float mu0 = mus[lane * MS + m],        lv0 = lvs[lane * MS + m];
            float mu1 = mus[(lane + 32) * MS + m], lv1 = lvs[(lane + 32) * MS + m];
            zs[lane * MS + m]        = ea[r] * __expf(0.5f * lv0) + mu0;
            zs[(lane + 32) * MS + m] = eb[r] * __expf(0.5f * lv1) + mu1;
        }
        __syncwarp();

        // ======== Phase 3: delta = z@Wnext^T, state update, totals ========
        #pragma unroll
        for (int r = 0; r < 2; ++r) {
            const int m = wrp * 2 + r;
            const int b = bBase + m;
            float d0 = bnx_s[lane], d1 = bnx_s[lane + 32];
            #pragma unroll 8
            for (int l = 0; l < LAT; ++l) {
                float zl = zs[l * MS + m];
                d0 = fmaf(zl, wnT[l * 64 + lane],      d0);
                d1 = fmaf(zl, wnT[l * 64 + lane + 32], d1);
            }
            float xn0 = (lane == 0) ? 0.f : fmaxf(xs[lane * MS + m] + d0, 0.f);
            float xn1 = fmaxf(xs[(lane + 32) * MS + m] + d1, 0.f);
            float part = xn0 + xn1;
            #pragma unroll
            for (int s2 = 16; s2 > 0; s2 >>= 1)
                part += __shfl_xor_sync(0xffffffffu, part, s2);
            float add = abuf[m];
            float v0 = (lane == 0) ? add : xn0;
            size_t ob = O_STATES + ((size_t)b * T_STEPS + t) * D_IN;
            out[ob + lane]      = v0;
            out[ob + lane + 32] = xn1;
            xs[lane * MS + m]        = v0;
            xs[(lane + 32) * MS + m] = xn1;
            if (lane == 0) {
                out[O_TPRE  + (size_t)b * 128 + t + 1] = part;
                out[O_TPOST + (size_t)b * 128 + t + 1] = part + add;
            }
        }
        __syncthreads();   // xs/hs/zs stable before next step's phase 1
    }
}

extern "C" void kernel_launch(void* const* d_in, const int* in_sizes, int n_in,
                              void* d_out, int out_size) {
    const float* data  = (const float*)d_in[0];
    const float* locs  = (const float*)d_in[1];
    const float* Wih   = (const float*)d_in[2];
    const float* Whh   = (const float*)d_in[3];
    const float* bih   = (const float*)d_in[4];
    const float* bhh   = (const float*)d_in[5];
    const float* Wmu   = (const float*)d_in[6];
    const float* bmu   = (const float*)d_in[7];
    const float* Wvar  = (const float*)d_in[8];
    const float* bvar  = (const float*)d_in[9];
    const float* Wvelo = (const float*)d_in[10];
    const float* bvelo = (const float*)d_in[11];
    const float* Wsw   = (const float*)d_in[12];
    const float* bsw   = (const float*)d_in[13];
    const float* Wgen  = (const float*)d_in[14];
    const float* bgen  = (const float*)d_in[15];
    const float* Won   = (const float*)d_in[16];
    const float* bon   = (const float*)d_in[17];
    const float* Wnext = (const float*)d_in[18];
    const float* bnext = (const float*)d_in[19];
    const float* Wloc  = (const float*)d_in[20];
    const float* bloc  = (const float*)d_in[21];
    const float* eps   = (const float*)d_in[22];
    float* out = (float*)d_out;

    prep_all_kernel<<<256, 512>>>(Wih, Whh, Wmu, Wvar,
                                  Wgen, bgen, Won, bon,
                                  Wvelo, bvelo, Wsw, bsw);

    const size_t smem_bytes = (size_t)SM_TOTF * sizeof(float);  // 114,496 B
    cudaFuncSetAttribute(model_kernel,
                         cudaFuncAttributeMaxDynamicSharedMemorySize,
                         (int)smem_bytes);
    model_kernel<<<NCTA, NTH, smem_bytes>>>(data, locs, bih, bhh,
                                            bmu, bvar, Wnext, bnext,
                                            Wloc, bloc, eps, out);
}

// round 14
// speedup vs baseline: 1.1112x; 1.1112x over previous
#include <cuda_runtime.h>

// Model_10582799417658: 127-step LSTM-VAE rollout.
// B=4096, D=64, H=256, GATES=1024, L=64, T=128 (127 scan steps).
//
// Round 14 (base = round-12 9327us winner; round-13 2-CTA experiment reverted):
//  - mus/lvs relocated to phase-1 slot1 (idle during phases 2a/2b/3)
//  - boundary prefetches: issue2(0) hides under phase-1 epilogue; next step's
//    issue1(0) hides under 2a-epilogue/2b/3 (weights are t-invariant).
// Inner loops byte-identical to round 12.

#define B_TOT   4096
#define T_STEPS 127
#define D_IN    64
#define HID     256
#define GATE    1024
#define LAT     64
#define BT      32
#define NTH     512
#define NCTA    (B_TOT / BT)   // 128
#define MS      36             // padded m-stride (floats)
#define NPP1    20             // phase-1 pairs (16 k each)
#define NPP2    4              // phase-2 pairs (64 k each)
#define SLOT1P  16384          // phase-1 pair-slot stride (floats, 64KB)
#define SLOT2P  8192           // phase-2 pair-slot stride (floats, 32KB)

// ---- output layout ----
#define N_STATES ((unsigned long long)B_TOT * T_STEPS * D_IN)
#define N_GENS   ((unsigned long long)B_TOT * T_STEPS)
#define N_TOTS   ((unsigned long long)B_TOT * 128)
#define O_STATES 0ULL
#define O_GENS   (O_STATES + N_STATES)
#define O_ONOFF  (O_GENS + N_GENS)
#define O_TPRE   (O_ONOFF + N_GENS)
#define O_TPOST  (O_TPRE + N_TOTS)

typedef unsigned long long ull;

__device__ float g_wgv[HID];
__device__ float g_wov[HID];
__device__ float g_b2[2];
// Phase-1 weights, k-major + gate-interleaved:
//   g_Wt1[k*1024 +       jp*4 + g*2 + jj] = Wg[(g  )*256 + jp*2 + jj][k], g in {0,1}
//   g_Wt1[k*1024 + 512 + jp*4 + g*2 + jj] = Wg[(g+2)*256 + jp*2 + jj][k], g in {0,1}
// where Wg row r: k<64 -> Wih[r][k], else Whh[r][k-64].
// Phase-2: g_Wt2[k][r] = (r<64 ? Wmu[r][k] : Wvar[r-64][k])
__device__ float g_Wt1[320 * 1024];
__device__ float g_Wt2[256 * 128];

__device__ __forceinline__ ull pack2s(float a) {   // splat (a, a)
    ull r;
    asm("mov.b64 %0, {%1,%1};" : "=l"(r) : "r"(__float_as_uint(a)));
    return r;
}
__device__ __forceinline__ void fma2(ull &d, ull a, ull b) {
    asm("fma.rn.f32x2 %0, %1, %2, %0;" : "+l"(d) : "l"(a), "l"(b));
}
__device__ __forceinline__ float2 unpack2(ull v) {
    unsigned int lo, hi;
    asm("mov.b64 {%0,%1}, %2;" : "=r"(lo), "=r"(hi) : "l"(v));
    float2 f; f.x = __uint_as_float(lo); f.y = __uint_as_float(hi);
    return f;
}
__device__ __forceinline__ float sig_f(float x) {
    return 1.0f / (1.0f + __expf(-x));
}
__device__ __forceinline__ float tanh_f(float x) {
    return 1.0f - 2.0f / (__expf(2.0f * x) + 1.0f);
}
__device__ __forceinline__ void cpa16(unsigned int dst, const void* src) {
    asm volatile("cp.async.cg.shared.global [%0], [%1], 16;" :: "r"(dst), "l"(src));
}
__device__ __forceinline__ void cpa_commit() {
    asm volatile("cp.async.commit_group;");
}
__device__ __forceinline__ void cpa_wait0() {
    asm volatile("cp.async.wait_group 0;");
}

// Merged one-time prep: rank-1 head folds + k-major weight transposes.
__global__ void prep_all_kernel(const float* __restrict__ Wih, const float* __restrict__ Whh,
                                const float* __restrict__ Wmu, const float* __restrict__ Wvar,
                                const float* __restrict__ Wgen, const float* __restrict__ bgen,
                                const float* __restrict__ Won,  const float* __restrict__ bon,
                                const float* __restrict__ Wvelo, const float* __restrict__ bvelo,
                                const float* __restrict__ Wsw,  const float* __restrict__ bsw) {
    const int stride = gridDim.x * blockDim.x;
    const int idx = blockIdx.x * blockDim.x + threadIdx.x;

    if (blockIdx.x == 0 && threadIdx.x < HID) {
        int k = threadIdx.x;
        float s1 = 0.f, s2 = 0.f;
        #pragma unroll 4
        for (int l = 0; l < LAT; ++l) {
            s1 += Wgen[l] * Wvelo[l * HID + k];
            s2 += Won[l]  * Wsw[l * HID + k];
        }
        g_wgv[k] = s1;
        g_wov[k] = s2;
        if (k == 0) {
            float b1 = bgen[0], b2 = bon[0];
            for (int l = 0; l < LAT; ++l) {
                b1 += Wgen[l] * bvelo[l];
                b2 += Won[l]  * bsw[l];
            }
            g_b2[0] = b1; g_b2[1] = b2;
        }
    }

    for (int i = idx; i < 320 * 1024; i += stride) {
        int k = i >> 10, d = i & 1023;
        int half = d >> 9, dd = d & 511;
        int jp = dd >> 2, q = dd & 3;
        int g = half * 2 + (q >> 1), jj = q & 1;
        int grow = g * 256 + jp * 2 + jj;
        g_Wt1[i] = (k < 64) ? Wih[grow * D_IN + k] : Whh[grow * HID + (k - 64)];
    }
    for (int i = idx; i < 256 * 128; i += stride) {
        int k = i >> 7, r = i & 127;
        g_Wt2[i] = (r < 64) ? Wmu[r * HID + k] : Wvar[(r - 64) * HID + k];
    }
}

__global__ void __launch_bounds__(NTH, 1)
model_kernel(const float* __restrict__ data, const float* __restrict__ locs,
             const float* __restrict__ bih,  const float* __restrict__ bhh,
             const float* __restrict__ bmu,  const float* __restrict__ bvar,
             const float* __restrict__ Wnext, const float* __restrict__ bnext,
             const float* __restrict__ Wloc, const float* __restrict__ bloc,
             const float* __restrict__ eps,  float* __restrict__ out) {
    extern __shared__ float sm[];
    float* xs     = sm;                  // [64][MS]
    float* hs     = xs     + 2304;       // [256][MS]  in-place h
    float* zs     = hs     + 9216;       // [64][MS]
    float* bsum   = zs     + 2304;       // [1024]
    float* wgv    = bsum   + 1024;       // [256]
    float* wov    = wgv    + 256;        // [256]
    float* bmu_s  = wov    + 256;        // [64]
    float* bvar_s = bmu_s  + 64;         // [64]
    float* bnx_s  = bvar_s + 64;         // [64]
    float* wnT    = bnx_s  + 64;         // [64][64]
    float* abuf   = wnT    + 4096;       // [32]
    float* wbA    = abuf   + 32;         // panel area: 2 x SLOT1P (32768 floats)
    // mus/lvs live in phase-1 slot1 (idle during phases 2a/2b/3); the next
    // step's early issue1(0) targets slot0 only, so these survive until read.
    float* mus    = wbA + SLOT1P;        // [64][MS]
    float* lvs    = wbA + SLOT1P + 2304; // [64][MS]

    const unsigned int wb_u32 =
        (unsigned int)__cvta_generic_to_shared(wbA);

    const int tid   = threadIdx.x;
    const int bBase = blockIdx.x * BT;
    // phase-1 tile: 4 m-tiles of 8 rows x 128 j-pairs (x4 gates)
    const int m0A  = (tid & 3) * 8;
    const int jp   = tid >> 2;           // 0..127
    const int jt2A = jp * 2;
    const int wrp = tid >> 5, lane = tid & 31;
    // phase-2a tile: 8 m-tiles of 4 x 64 row-pairs
    const int m08 = (tid & 7) * 4;
    const int jq2 = (tid >> 3) * 2;      // 0..126

    // ---------------- init ----------------
    for (int i = tid; i < D_IN * BT; i += NTH) {
        int k = i / BT, m = i % BT;
        xs[k * MS + m] = data[(size_t)(bBase + m) * (128 * D_IN) + k];
    }
    for (int i = tid; i < HID * BT; i += NTH) {
        int j = i / BT, m = i % BT;
        int b = bBase + m;
        hs[j * MS + m] = locs[b * 2] * Wloc[j * 2] + locs[b * 2 + 1] * Wloc[j * 2 + 1] + bloc[j];
    }
    for (int i = tid; i < GATE; i += NTH) bsum[i] = bih[i] + bhh[i];
    for (int i = tid; i < HID; i += NTH) { wgv[i] = g_wgv[i]; wov[i] = g_wov[i]; }
    for (int i = tid; i < LAT; i += NTH) { bmu_s[i] = bmu[i]; bvar_s[i] = bvar[i]; }
    for (int i = tid; i < D_IN; i += NTH) bnx_s[i] = bnext[i];
    for (int i = tid; i < LAT * D_IN; i += NTH) {   // wnT[l][c] = Wnext[c][l]
        int l = i >> 6, c = i & 63;
        wnT[i] = Wnext[c * LAT + l];
    }
    if (tid < BT) {
        out[O_TPRE  + (size_t)(bBase + tid) * 128] = 0.f;
        out[O_TPOST + (size_t)(bBase + tid) * 128] = 0.f;
    }
    const float bgv = g_b2[0], bov = g_b2[1];

    // c state in registers: thread owns cols (jt2A, jt2A+1) x rows m0A..m0A+7
    float c_reg[16];
    #pragma unroll
    for (int i = 0; i < 16; ++i) c_reg[i] = 0.f;
    __syncthreads();

    // pair issue helpers (cp.async, 16B granules)
    auto issue1 = [&](int pp, int slot) {   // 16384 floats = 8 x 512 float4
        const float4* src = ((const float4*)g_Wt1) + (size_t)pp * 4096 + tid;
        unsigned int dst = wb_u32 + (unsigned int)slot * (SLOT1P * 4u) + tid * 16u;
        #pragma unroll
        for (int i = 0; i < 8; ++i)
            cpa16(dst + (unsigned int)i * 8192u, src + i * 512);
    };
    auto issue2 = [&](int pp, int slot) {   // 8192 floats = 4 x 512 float4
        const float4* src = ((const float4*)g_Wt2) + (size_t)pp * 2048 + tid;
        unsigned int dst = wb_u32 + (unsigned int)slot * (SLOT2P * 4u) + tid * 16u;
        #pragma unroll
        for (int i = 0; i < 4; ++i)
            cpa16(dst + (unsigned int)i * 8192u, src + i * 512);
    };

    // pre-issue phase-1 pair 0 for step 0 (weights are t-invariant)
    issue1(0, 0); cpa_commit();

    for (int t = 0; t < T_STEPS; ++t) {
        // prefetch eps for phase 2b
        float ea[2], eb[2];
        {
            const int mr = wrp * 2;
            const float* ep = eps + ((size_t)t * B_TOT + bBase + mr) * LAT;
            ea[0] = __ldg(ep + lane);        eb[0] = __ldg(ep + lane + 32);
            ea[1] = __ldg(ep + LAT + lane);  eb[1] = __ldg(ep + LAT + lane + 32);
        }

        // ======== Phase 1: gates = x@Wih^T + h@Whh^T, LSTM update ========
        {
            ull acc[32];
            #pragma unroll
            for (int i = 0; i < 32; ++i) acc[i] = 0ULL;

            for (int pp = 0; pp < NPP1; ++pp) {
                cpa_wait0();         // pair pp arrived (this thread's copies)
                __syncthreads();     // visible to all; pair pp-1 fully consumed
                if (pp + 1 < NPP1) { issue1(pp + 1, (pp + 1) & 1); cpa_commit(); }
                const float* wc = wbA + (pp & 1) * SLOT1P;
                const float* Ab = (pp < 4) ? (xs + pp * 16 * MS)
                                           : (hs + (pp * 16 - 64) * MS);
                #pragma unroll
                for (int kk = 0; kk < 16; ++kk) {
                    float4 a0 = *(const float4*)(Ab + kk * MS + m0A);
                    float4 a1 = *(const float4*)(Ab + kk * MS + m0A + 4);
                    const float* wr = wc + kk * 1024 + jp * 4;
                    ulonglong2 wA = *(const ulonglong2*)(wr);        // g0, g1
                    ulonglong2 wB = *(const ulonglong2*)(wr + 512);  // g2, g3
                    ull w0 = wA.x, w1 = wA.y, w2 = wB.x, w3 = wB.y;
                    #pragma unroll
                    for (int m = 0; m < 4; ++m) {
                        ull am = pack2s((&a0.x)[m]);
                        fma2(acc[m * 4 + 0], am, w0);
                        fma2(acc[m * 4 + 1], am, w1);
                        fma2(acc[m * 4 + 2], am, w2);
                        fma2(acc[m * 4 + 3], am, w3);
                    }
                    #pragma unroll
                    for (int m = 0; m < 4; ++m) {
                        ull am = pack2s((&a1.x)[m]);
                        fma2(acc[(m + 4) * 4 + 0], am, w0);
                        fma2(acc[(m + 4) * 4 + 1], am, w1);
                        fma2(acc[(m + 4) * 4 + 2], am, w2);
                        fma2(acc[(m + 4) * 4 + 3], am, w3);
                    }
                }
            }
            __syncthreads();         // all warps done reading hs/panels

            // boundary prefetch: phase-2a pair 0 -> phase-2 slot0 (inside
            // phase-1 slot0, whose pair 18 is long consumed). Hides under
            // the 32-MUFU epilogue below.
            issue2(0, 0); cpa_commit();

            // epilogue: bias + LSTM nonlinearity; c in regs, h in place
            const int hj0 = jt2A, hj1 = jt2A + 1;
            const float bi0 = bsum[hj0],       bi1 = bsum[hj1];
            const float bf0 = bsum[256 + hj0], bf1 = bsum[256 + hj1];
            const float bg0 = bsum[512 + hj0], bg1 = bsum[512 + hj1];
            const float bo0 = bsum[768 + hj0], bo1 = bsum[768 + hj1];
            #pragma unroll
            for (int m = 0; m < 8; ++m) {
                const int mm = m0A + m;
                float2 vi = unpack2(acc[m * 4 + 0]);
                float2 vf = unpack2(acc[m * 4 + 1]);
                float2 vg = unpack2(acc[m * 4 + 2]);
                float2 vo = unpack2(acc[m * 4 + 3]);
                {
                    float iv = sig_f(vi.x + bi0), fv = sig_f(vf.x + bf0);
                    float gv = tanh_f(vg.x + bg0), ov = sig_f(vo.x + bo0);
                    float c = fv * c_reg[m * 2 + 0] + iv * gv;
                    c_reg[m * 2 + 0] = c;
                    hs[hj0 * MS + mm] = ov * tanh_f(c);
                }
                {
                    float iv = sig_f(vi.y + bi1), fv = sig_f(vf.y + bf1);
                    float gv = tanh_f(vg.y + bg1), ov = sig_f(vo.y + bo1);
                    float c = fv * c_reg[m * 2 + 1] + iv * gv;
                    c_reg[m * 2 + 1] = c;
                    hs[hj1 * MS + mm] = ov * tanh_f(c);
                }
            }
        }

        // ======== Phase 2a: [mu;logvar] = h @ [Wmu;Wvar]^T ========
        {
            ull acc2[4] = {0ULL, 0ULL, 0ULL, 0ULL};

            for (int pp = 0; pp < NPP2; ++pp) {
                cpa_wait0();
                __syncthreads();     // also orders phase-1 hs epilogue writes
                if (pp + 1 < NPP2) { issue2(pp + 1, (pp + 1) & 1); cpa_commit(); }
                const float* wc = wbA + (pp & 1) * SLOT2P;
                const int k0 = pp * 64;
                #pragma unroll 16
                for (int kk = 0; kk < 64; ++kk) {
                    float4 a = *(const float4*)(hs + (k0 + kk) * MS + m08);
                    ull w = *(const ull*)(wc + kk * 128 + jq2);
                    fma2(acc2[0], pack2s(a.x), w);
                    fma2(acc2[1], pack2s(a.y), w);
                    fma2(acc2[2], pack2s(a.z), w);
                    fma2(acc2[3], pack2s(a.w), w);
                }
            }
            __syncthreads();         // all warps done with panel slots

            // boundary prefetch: next step's phase-1 pair 0 -> slot0.
            // Same bytes every step; hides under 2a epilogue + 2b + 3.
            // mus/lvs live in slot1, untouched by this copy.
            issue1(0, 0); cpa_commit();

            // epilogue: row pair (jq2, jq2+1) for 4 m rows -> mus/lvs (slot1)
            if (jq2 < 64) {
                const float b0 = bmu_s[jq2], b1 = bmu_s[jq2 + 1];
                #pragma unroll
                for (int m = 0; m < 4; ++m) {
                    float2 v = unpack2(acc2[m]);
                    mus[jq2 * MS + m08 + m]       = v.x + b0;
                    mus[(jq2 + 1) * MS + m08 + m] = v.y + b1;
                }
            } else {
                const int l0 = jq2 - 64;
                const float b0 = bvar_s[l0], b1 = bvar_s[l0 + 1];
                #pragma unroll
                for (int m = 0; m < 4; ++m) {
                    float2 v = unpack2(acc2[m]);
                    lvs[l0 * MS + m08 + m]       = v.x + b0;
                    lvs[(l0 + 1) * MS + m08 + m] = v.y + b1;
                }
            }
        }
        __syncthreads();

        // ======== Phase 2b: gen/on + reparameterized z ========
        #pragma unroll
        for (int r = 0; r < 2; ++r) {
            const int m = wrp * 2 + r;
            const int b = bBase + m;
            float gp = 0.f, op = 0.f;
            #pragma unroll
            for (int i2 = 0; i2 < 8; ++i2) {
                int k = lane + 32 * i2;
                float hv = hs[k * MS + m];
                gp = fmaf(hv, wgv[k], gp);
                op = fmaf(hv, wov[k], op);
            }
            #pragma unroll
            for (int s2 = 16; s2 > 0; s2 >>= 1) {
                gp += __shfl_xor_sync(0xffffffffu, gp, s2);
                op += __shfl_xor_sync(0xffffffffu, op, s2);
            }
            if (lane == 0) {
                float gen = fmaxf(gp + bgv, 0.f);
                float on  = (op + bov) > 0.f ? 1.f : 0.f;
                abuf[m] = gen * on;
                out[O_GENS  + (size_t)b * T_STEPS + t] = gen;
                out[O_ONOFF + (size_t)b * T_STEPS + t] = on;
            }
            float mu0 = mus[lane * MS + m],        lv0 = lvs[lane * MS + m];
            float mu1 = mus[(lane + 32) * MS + m], lv1 = lvs[(lane + 32) * MS + m];
            zs[lane * MS + m]        = ea[r] * __expf(0.5f * lv0) + mu0;
            zs[(lane + 32) * MS + m] = eb[r] * __expf(0.5f * lv1) + mu1;
        }
        __syncwarp();

        // ======== Phase 3: delta = z@Wnext^T, state update, totals ========
        #pragma unroll
        for (int r = 0; r < 2; ++r) {
            const int m = wrp * 2 + r;
            const int b = bBase + m;
            float d0 = bnx_s[lane], d1 = bnx_s[lane + 32];
            #pragma unroll 8
            for (int l = 0; l < LAT; ++l) {
                float zl = zs[l * MS + m];
                d0 = fmaf(zl, wnT[l * 64 + lane],      d0);
                d1 = fmaf(zl, wnT[l * 64 + lane + 32], d1);
            }
            float xn0 = (lane == 0) ? 0.f : fmaxf(xs[lane * MS + m] + d0, 0.f);
            float xn1 = fmaxf(xs[(lane + 32) * MS + m] + d1, 0.f);
            float part = xn0 + xn1;
            #pragma unroll
            for (int s2 = 16; s2 > 0; s2 >>= 1)
                part += __shfl_xor_sync(0xffffffffu, part, s2);
            float add = abuf[m];
            float v0 = (lane == 0) ? add : xn0;
            size_t ob = O_STATES + ((size_t)b * T_STEPS + t) * D_IN;
            out[ob + lane]      = v0;
            out[ob + lane + 32] = xn1;
            xs[lane * MS + m]        = v0;
            xs[(lane + 32) * MS + m] = xn1;
            if (lane == 0) {
                out[O_TPRE  + (size_t)b * 128 + t + 1] = part;
                out[O_TPOST + (size_t)b * 128 + t + 1] = part + add;
            }
        }
        __syncthreads();   // xs/hs/mus/lvs stable before next step's phase 1
    }
}

extern "C" void kernel_launch(void* const* d_in, const int* in_sizes, int n_in,
                              void* d_out, int out_size) {
    const float* data  = (const float*)d_in[0];
    const float* locs  = (const float*)d_in[1];
    const float* Wih   = (const float*)d_in[2];
    const float* Whh   = (const float*)d_in[3];
    const float* bih   = (const float*)d_in[4];
    const float* bhh   = (const float*)d_in[5];
    const float* Wmu   = (const float*)d_in[6];
    const float* bmu   = (const float*)d_in[7];
    const float* Wvar  = (const float*)d_in[8];
    const float* bvar  = (const float*)d_in[9];
    const float* Wvelo = (const float*)d_in[10];
    const float* bvelo = (const float*)d_in[11];
    const float* Wsw   = (const float*)d_in[12];
    const float* bsw   = (const float*)d_in[13];
    const float* Wgen  = (const float*)d_in[14];
    const float* bgen  = (const float*)d_in[15];
    const float* Won   = (const float*)d_in[16];
    const float* bon   = (const float*)d_in[17];
    const float* Wnext = (const float*)d_in[18];
    const float* bnext = (const float*)d_in[19];
    const float* Wloc  = (const float*)d_in[20];
    const float* bloc  = (const float*)d_in[21];
    const float* eps   = (const float*)d_in[22];
    float* out = (float*)d_out;

    prep_all_kernel<<<256, 512>>>(Wih, Whh, Wmu, Wvar,
                                  Wgen, bgen, Won, bon,
                                  Wvelo, bvelo, Wsw, bsw);

    // floats: 19680 (state) + 2 * 16384 (pair slots) = 52448
    const size_t smem_bytes = 52448 * sizeof(float);  // 209,792 B
    cudaFuncSetAttribute(model_kernel,
                         cudaFuncAttributeMaxDynamicSharedMemorySize,
                         (int)smem_bytes);
    model_kernel<<<NCTA, NTH, smem_bytes>>>(data, locs, bih, bhh,
                                            bmu, bvar, Wnext, bnext,
                                            Wloc, bloc, eps, out);
}

// round 15
// speedup vs baseline: 1.1292x; 1.0162x over previous
#include <cuda_runtime.h>

// Model_10582799417658: 127-step LSTM-VAE rollout.
// B=4096, D=64, H=256, GATES=1024, L=64, T=128 (127 scan steps).
//
// Round 15 (base = round-12 9327us): phase-1 GEMM moved to tensor cores via
// 3xTF32 mma.sync.m16n8k8 (ah*bh + ah*bl + al*bh; fp32-level accuracy, so the
// on/off threshold outputs don't flip). Weights pre-split hi/lo in prep with
// k-pair interleaving (B-frag = 1 LDS.64). Gate-strided n-tiling keeps all 4
// gates of a hidden j in one thread -> epilogue/c_reg unchanged. Phases
// 2a/2b/3 and the cp.async ring are round-12 verbatim.

#define B_TOT   4096
#define T_STEPS 127
#define D_IN    64
#define HID     256
#define GATE    1024
#define LAT     64
#define BT      32
#define NTH     512
#define NCTA    (B_TOT / BT)   // 128
#define MS      36             // padded m-stride (floats)
#define NP1     40             // phase-1 panels (one 8-k chunk, hi+lo planes)
#define NPP2    4              // phase-2 pairs (64 k each)
#define SLOT1P  16384          // phase-1 slot stride (floats, 64KB)
#define SLOT2P  8192           // phase-2 slot stride (floats, 32KB)

// ---- output layout ----
#define N_STATES ((unsigned long long)B_TOT * T_STEPS * D_IN)
#define N_GENS   ((unsigned long long)B_TOT * T_STEPS)
#define N_TOTS   ((unsigned long long)B_TOT * 128)
#define O_STATES 0ULL
#define O_GENS   (O_STATES + N_STATES)
#define O_ONOFF  (O_GENS + N_GENS)
#define O_TPRE   (O_ONOFF + N_GENS)
#define O_TPOST  (O_TPRE + N_TOTS)

typedef unsigned long long ull;

__device__ float g_wgv[HID];
__device__ float g_wov[HID];
__device__ float g_b2[2];
// Phase-1 weights, tf32 hi/lo split, fragment-interleaved:
//   flat float i: comp=i&1, f2=i>>1, p=f2&3, n=(f2>>2)&1023,
//                 pl=(f2>>12)&1, kc=f2>>13, k=kc*8+p+comp*4
//   value = pl==0 ? tf32(W[n][k]) : tf32(W[n][k]-tf32(W[n][k]))
//   where W row n: k<64 -> Wih[n][k], else Whh[n][k-64].
// Per-chunk layout (16384 floats): [pl][n][p] as float2 pairs (k, k+4).
__device__ float g_Wt1[40 * 16384];
// Phase-2: g_Wt2[k][r] = (r<64 ? Wmu[r][k] : Wvar[r-64][k])
__device__ float g_Wt2[256 * 128];

__device__ __forceinline__ ull pack2s(float a) {   // splat (a, a)
    ull r;
    asm("mov.b64 %0, {%1,%1};" : "=l"(r) : "r"(__float_as_uint(a)));
    return r;
}
__device__ __forceinline__ void fma2(ull &d, ull a, ull b) {
    asm("fma.rn.f32x2 %0, %1, %2, %0;" : "+l"(d) : "l"(a), "l"(b));
}
__device__ __forceinline__ float2 unpack2(ull v) {
    unsigned int lo, hi;
    asm("mov.b64 {%0,%1}, %2;" : "=r"(lo), "=r"(hi) : "l"(v));
    float2 f; f.x = __uint_as_float(lo); f.y = __uint_as_float(hi);
    return f;
}
__device__ __forceinline__ float sig_f(float x) {
    return 1.0f / (1.0f + __expf(-x));
}
__device__ __forceinline__ float tanh_f(float x) {
    return 1.0f - 2.0f / (__expf(2.0f * x) + 1.0f);
}
__device__ __forceinline__ float tf32r(float x) {   // round-to-nearest tf32
    unsigned int r;
    asm("cvt.rna.tf32.f32 %0, %1;" : "=r"(r) : "f"(x));
    return __uint_as_float(r);
}
__device__ __forceinline__ void mma_tf32(float* d, const float* a, float2 b) {
    asm volatile(
        "mma.sync.aligned.m16n8k8.row.col.f32.tf32.tf32.f32 "
        "{%0,%1,%2,%3}, {%4,%5,%6,%7}, {%8,%9}, {%0,%1,%2,%3};"
        : "+f"(d[0]), "+f"(d[1]), "+f"(d[2]), "+f"(d[3])
        : "r"(__float_as_uint(a[0])), "r"(__float_as_uint(a[1])),
          "r"(__float_as_uint(a[2])), "r"(__float_as_uint(a[3])),
          "r"(__float_as_uint(b.x)),  "r"(__float_as_uint(b.y)));
}
__device__ __forceinline__ void cpa16(unsigned int dst, const void* src) {
    asm volatile("cp.async.cg.shared.global [%0], [%1], 16;" :: "r"(dst), "l"(src));
}
__device__ __forceinline__ void cpa_commit() {
    asm volatile("cp.async.commit_group;");
}
__device__ __forceinline__ void cpa_wait0() {
    asm volatile("cp.async.wait_group 0;");
}

// Merged one-time prep: rank-1 head folds + weight transforms.
__global__ void prep_all_kernel(const float* __restrict__ Wih, const float* __restrict__ Whh,
                                const float* __restrict__ Wmu, const float* __restrict__ Wvar,
                                const float* __restrict__ Wgen, const float* __restrict__ bgen,
                                const float* __restrict__ Won,  const float* __restrict__ bon,
                                const float* __restrict__ Wvelo, const float* __restrict__ bvelo,
                                const float* __restrict__ Wsw,  const float* __restrict__ bsw) {
    const int stride = gridDim.x * blockDim.x;
    const int idx = blockIdx.x * blockDim.x + threadIdx.x;

    if (blockIdx.x == 0 && threadIdx.x < HID) {
        int k = threadIdx.x;
        float s1 = 0.f, s2 = 0.f;
        #pragma unroll 4
        for (int l = 0; l < LAT; ++l) {
            s1 += Wgen[l] * Wvelo[l * HID + k];
            s2 += Won[l]  * Wsw[l * HID + k];
        }
        g_wgv[k] = s1;
        g_wov[k] = s2;
        if (k == 0) {
            float b1 = bgen[0], b2 = bon[0];
            for (int l = 0; l < LAT; ++l) {
                b1 += Wgen[l] * bvelo[l];
                b2 += Won[l]  * bsw[l];
            }
            g_b2[0] = b1; g_b2[1] = b2;
        }
    }

    for (int i = idx; i < 40 * 16384; i += stride) {
        int comp = i & 1, f2 = i >> 1;
        int p_ = f2 & 3, n = (f2 >> 2) & 1023, pl = (f2 >> 12) & 1, kc = f2 >> 13;
        int k = kc * 8 + p_ + comp * 4;
        float w = (k < 64) ? Wih[n * D_IN + k] : Whh[n * HID + (k - 64)];
        float hi = tf32r(w);
        g_Wt1[i] = (pl == 0) ? hi : tf32r(w - hi);
    }
    for (int i = idx; i < 256 * 128; i += stride) {
        int k = i >> 7, r = i & 127;
        g_Wt2[i] = (r < 64) ? Wmu[r * HID + k] : Wvar[(r - 64) * HID + k];
    }
}

__global__ void __launch_bounds__(NTH, 1)
model_kernel(const float* __restrict__ data, const float* __restrict__ locs,
             const float* __restrict__ bih,  const float* __restrict__ bhh,
             const float* __restrict__ bmu,  const float* __restrict__ bvar,
             const float* __restrict__ Wnext, const float* __restrict__ bnext,
             const float* __restrict__ Wloc, const float* __restrict__ bloc,
             const float* __restrict__ eps,  float* __restrict__ out) {
    extern __shared__ float sm[];
    float* xs     = sm;                  // [64][MS]
    float* hs     = xs     + 2304;       // [256][MS]  in-place h
    float* zs     = hs     + 9216;       // [64][MS]
    float* bsum   = zs     + 2304;       // [1024]
    float* wgv    = bsum   + 1024;       // [256]
    float* wov    = wgv    + 256;        // [256]
    float* bmu_s  = wov    + 256;        // [64]
    float* bvar_s = bmu_s  + 64;         // [64]
    float* bnx_s  = bvar_s + 64;         // [64]
    float* wnT    = bnx_s  + 64;         // [64][64]
    float* abuf   = wnT    + 4096;       // [32]
    float* wbA    = abuf   + 32;         // panel area: 2 x SLOT1P (32768 floats)
    float* mus    = wbA;                 // [64][MS]  (reuse after phase 2a)
    float* lvs    = wbA + 2304;          // [64][MS]

    const unsigned int wb_u32 =
        (unsigned int)__cvta_generic_to_shared(wbA);

    const int tid   = threadIdx.x;
    const int bBase = blockIdx.x * BT;
    const int wrp = tid >> 5, lane = tid & 31;
    const int qg = lane >> 2;            // mma group id (0..7)
    const int tq = lane & 3;             // thread-in-group (0..3)
    // phase-2a tile: 8 m-tiles of 4 x 64 row-pairs
    const int m08 = (tid & 7) * 4;
    const int jq2 = (tid >> 3) * 2;      // 0..126

    // ---------------- init ----------------
    for (int i = tid; i < D_IN * BT; i += NTH) {
        int k = i / BT, m = i % BT;
        xs[k * MS + m] = data[(size_t)(bBase + m) * (128 * D_IN) + k];
    }
    for (int i = tid; i < HID * BT; i += NTH) {
        int j = i / BT, m = i % BT;
        int b = bBase + m;
        hs[j * MS + m] = locs[b * 2] * Wloc[j * 2] + locs[b * 2 + 1] * Wloc[j * 2 + 1] + bloc[j];
    }
    for (int i = tid; i < GATE; i += NTH) bsum[i] = bih[i] + bhh[i];
    for (int i = tid; i < HID; i += NTH) { wgv[i] = g_wgv[i]; wov[i] = g_wov[i]; }
    for (int i = tid; i < LAT; i += NTH) { bmu_s[i] = bmu[i]; bvar_s[i] = bvar[i]; }
    for (int i = tid; i < D_IN; i += NTH) bnx_s[i] = bnext[i];
    for (int i = tid; i < LAT * D_IN; i += NTH) {   // wnT[l][c] = Wnext[c][l]
        int l = i >> 6, c = i & 63;
        wnT[i] = Wnext[c * LAT + l];
    }
    if (tid < BT) {
        out[O_TPRE  + (size_t)(bBase + tid) * 128] = 0.f;
        out[O_TPOST + (size_t)(bBase + tid) * 128] = 0.f;
    }
    const float bgv = g_b2[0], bov = g_b2[1];

    // c state in registers: thread owns, per (s,mt,rh), the j-pair
    // j0 = wrp*16 + s*8 + tq*2 at row m = mt*16 + qg + rh*8.
    float c_reg[16];
    #pragma unroll
    for (int i = 0; i < 16; ++i) c_reg[i] = 0.f;
    __syncthreads();

    // panel issue helpers (cp.async, 16B granules)
    auto issue1 = [&](int p, int slot) {    // 16384 floats = 8 x 512 float4
        const float4* src = ((const float4*)g_Wt1) + (size_t)p * 4096 + tid;
        unsigned int dst = wb_u32 + (unsigned int)slot * (SLOT1P * 4u) + tid * 16u;
        #pragma unroll
        for (int i = 0; i < 8; ++i)
            cpa16(dst + (unsigned int)i * 8192u, src + i * 512);
    };
    auto issue2 = [&](int pp, int slot) {   // 8192 floats = 4 x 512 float4
        const float4* src = ((const float4*)g_Wt2) + (size_t)pp * 2048 + tid;
        unsigned int dst = wb_u32 + (unsigned int)slot * (SLOT2P * 4u) + tid * 16u;
        #pragma unroll
        for (int i = 0; i < 4; ++i)
            cpa16(dst + (unsigned int)i * 8192u, src + i * 512);
    };

    for (int t = 0; t < T_STEPS; ++t) {
        // prefetch eps for phase 2b
        float ea[2], eb[2];
        {
            const int mr = wrp * 2;
            const float* ep = eps + ((size_t)t * B_TOT + bBase + mr) * LAT;
            ea[0] = __ldg(ep + lane);        eb[0] = __ldg(ep + lane + 32);
            ea[1] = __ldg(ep + LAT + lane);  eb[1] = __ldg(ep + LAT + lane + 32);
        }

        // ======== Phase 1: gates GEMM via 3xTF32 mma, LSTM update ========
        {
            issue1(0, 0); cpa_commit();

            float dacc[2][8][4];
            #pragma unroll
            for (int a = 0; a < 2; ++a)
                #pragma unroll
                for (int b = 0; b < 8; ++b)
                    #pragma unroll
                    for (int c = 0; c < 4; ++c) dacc[a][b][c] = 0.f;

            for (int p = 0; p < NP1; ++p) {
                cpa_wait0();         // panel p arrived
                __syncthreads();     // visible to all; panel p-1 fully consumed
                if (p + 1 < NP1) { issue1(p + 1, (p + 1) & 1); cpa_commit(); }
                const float* wc = wbA + (p & 1) * SLOT1P;
                const float* Ab = (p < 8) ? (xs + p * 8 * MS)
                                          : (hs + (p * 8 - 64) * MS);
                #pragma unroll
                for (int mt = 0; mt < 2; ++mt) {
                    // A fragment (m16 x k8) + on-the-fly hi/lo split
                    float ah[4], al[4];
                    #pragma unroll
                    for (int r = 0; r < 4; ++r) {
                        int c = ((r >> 1) << 2) + tq;          // k within chunk
                        int m = mt * 16 + qg + ((r & 1) << 3); // batch row
                        float a = Ab[c * MS + m];
                        ah[r] = tf32r(a);
                        al[r] = tf32r(a - ah[r]);
                    }
                    #pragma unroll
                    for (int nf = 0; nf < 8; ++nf) {   // nf = gate*2 + s
                        int g = nf >> 1, s = nf & 1;
                        int n = (g << 8) + wrp * 16 + (s << 3) + qg;
                        const float2* bp = (const float2*)wc + n * 4 + tq;
                        float2 BH = bp[0];
                        float2 BL = bp[4096];          // lo plane (+8192 floats)
                        float* D = dacc[mt][nf];
                        mma_tf32(D, ah, BH);
                        mma_tf32(D, ah, BL);
                        mma_tf32(D, al, BH);
                    }
                }
            }
            __syncthreads();         // all warps done reading hs/panels

            // epilogue: bias + LSTM nonlinearity; c in regs, h in place
            #pragma unroll
            for (int s = 0; s < 2; ++s) {
                const int j0 = wrp * 16 + (s << 3) + (tq << 1);
                const int j1 = j0 + 1;
                const float bi0 = bsum[j0],       bi1 = bsum[j1];
                const float bf0 = bsum[256 + j0], bf1 = bsum[256 + j1];
                const float bg0 = bsum[512 + j0], bg1 = bsum[512 + j1];
                const float bo0 = bsum[768 + j0], bo1 = bsum[768 + j1];
                #pragma unroll
                for (int mt = 0; mt < 2; ++mt) {
                    #pragma unroll
                    for (int rh = 0; rh < 2; ++rh) {
                        const int m = mt * 16 + qg + (rh << 3);
                        const int cb = ((((s << 1) | mt) << 1) | rh) << 1;
                        {
                            float iv = sig_f(dacc[mt][0 + s][rh * 2] + bi0);
                            float fv = sig_f(dacc[mt][2 + s][rh * 2] + bf0);
                            float gv = tanh_f(dacc[mt][4 + s][rh * 2] + bg0);
                            float ov = sig_f(dacc[mt][6 + s][rh * 2] + bo0);
                            float c = fv * c_reg[cb] + iv * gv;
                            c_reg[cb] = c;
                            hs[j0 * MS + m] = ov * tanh_f(c);
                        }
                        {
                            float iv = sig_f(dacc[mt][0 + s][rh * 2 + 1] + bi1);
                            float fv = sig_f(dacc[mt][2 + s][rh * 2 + 1] + bf1);
                            float gv = tanh_f(dacc[mt][4 + s][rh * 2 + 1] + bg1);
                            float ov = sig_f(dacc[mt][6 + s][rh * 2 + 1] + bo1);
                            float c = fv * c_reg[cb + 1] + iv * gv;
                            c_reg[cb + 1] = c;
                            hs[j1 * MS + m] = ov * tanh_f(c);
                        }
                    }
                }
            }
        }

        // ======== Phase 2a: [mu;logvar] = h @ [Wmu;Wvar]^T (FFMA2) ========
        {
            issue2(0, 0); cpa_commit();

            ull acc2[4] = {0ULL, 0ULL, 0ULL, 0ULL};

            for (int pp = 0; pp < NPP2; ++pp) {
                cpa_wait0();
                __syncthreads();     // also orders phase-1 hs epilogue writes
                if (pp + 1 < NPP2) { issue2(pp + 1, (pp + 1) & 1); cpa_commit(); }
                const float* wc = wbA + (pp & 1) * SLOT2P;
                const int k0 = pp * 64;
                #pragma unroll 16
                for (int kk = 0; kk < 64; ++kk) {
                    float4 a = *(const float4*)(hs + (k0 + kk) * MS + m08);
                    ull w = *(const ull*)(wc + kk * 128 + jq2);
                    fma2(acc2[0], pack2s(a.x), w);
                    fma2(acc2[1], pack2s(a.y), w);
                    fma2(acc2[2], pack2s(a.z), w);
                    fma2(acc2[3], pack2s(a.w), w);
                }
            }
            __syncthreads();         // all warps done with panel slots

            // epilogue: row pair (jq2, jq2+1) for 4 m rows -> mus/lvs (slot0)
            if (jq2 < 64) {
                const float b0 = bmu_s[jq2], b1 = bmu_s[jq2 + 1];
                #pragma unroll
                for (int m = 0; m < 4; ++m) {
                    float2 v = unpack2(acc2[m]);
                    mus[jq2 * MS + m08 + m]       = v.x + b0;
                    mus[(jq2 + 1) * MS + m08 + m] = v.y + b1;
                }
            } else {
                const int l0 = jq2 - 64;
                const float b0 = bvar_s[l0], b1 = bvar_s[l0 + 1];
                #pragma unroll
                for (int m = 0; m < 4; ++m) {
                    float2 v = unpack2(acc2[m]);
                    lvs[l0 * MS + m08 + m]       = v.x + b0;
                    lvs[(l0 + 1) * MS + m08 + m] = v.y + b1;
                }
            }
        }
        __syncthreads();

        // ======== Phase 2b: gen/on + reparameterized z ========
        #pragma unroll
        for (int r = 0; r < 2; ++r) {
            const int m = wrp * 2 + r;
            const int b = bBase + m;
            float gp = 0.f, op = 0.f;
            #pragma unroll
            for (int i2 = 0; i2 < 8; ++i2) {
                int k = lane + 32 * i2;
                float hv = hs[k * MS + m];
                gp = fmaf(hv, wgv[k], gp);
                op = fmaf(hv, wov[k], op);
            }
            #pragma unroll
            for (int s2 = 16; s2 > 0; s2 >>= 1) {
                gp += __shfl_xor_sync(0xffffffffu, gp, s2);
                op += __shfl_xor_sync(0xffffffffu, op, s2);
            }
            if (lane == 0) {
                float gen = fmaxf(gp + bgv, 0.f);
                float on  = (op + bov) > 0.f ? 1.f : 0.f;
                abuf[m] = gen * on;
                out[O_GENS  + (size_t)b * T_STEPS + t] = gen;
                out[O_ONOFF + (size_t)b * T_STEPS + t] = on;
            }
            float mu0 = mus[lane * MS + m],        lv0 = lvs[lane * MS + m];
            float mu1 = mus[(lane + 32) * MS + m], lv1 = lvs[(lane + 32) * MS + m];
            zs[lane * MS + m]        = ea[r] * __expf(0.5f * lv0) + mu0;
            zs[(lane + 32) * MS + m] = eb[r] * __expf(0.5f * lv1) + mu1;
        }
        __syncwarp();

        // ======== Phase 3: delta = z@Wnext^T, state update, totals ========
        #pragma unroll
        for (int r = 0; r < 2; ++r) {
            const int m = wrp * 2 + r;
            const int b = bBase + m;
            float d0 = bnx_s[lane], d1 = bnx_s[lane + 32];
            #pragma unroll 8
            for (int l = 0; l < LAT; ++l) {
                float zl = zs[l * MS + m];
                d0 = fmaf(zl, wnT[l * 64 + lane],      d0);
                d1 = fmaf(zl, wnT[l * 64 + lane + 32], d1);
            }
            float xn0 = (lane == 0) ? 0.f : fmaxf(xs[lane * MS + m] + d0, 0.f);
            float xn1 = fmaxf(xs[(lane + 32) * MS + m] + d1, 0.f);
            float part = xn0 + xn1;
            #pragma unroll
            for (int s2 = 16; s2 > 0; s2 >>= 1)
                part += __shfl_xor_sync(0xffffffffu, part, s2);
            float add = abuf[m];
            float v0 = (lane == 0) ? add : xn0;
            size_t ob = O_STATES + ((size_t)b * T_STEPS + t) * D_IN;
            out[ob + lane]      = v0;
            out[ob + lane + 32] = xn1;
            xs[lane * MS + m]        = v0;
            xs[(lane + 32) * MS + m] = xn1;
            if (lane == 0) {
                out[O_TPRE  + (size_t)b * 128 + t + 1] = part;
                out[O_TPOST + (size_t)b * 128 + t + 1] = part + add;
            }
        }
        __syncthreads();   // xs/hs stable before next step's phase 1
    }
}

extern "C" void kernel_launch(void* const* d_in, const int* in_sizes, int n_in,
                              void* d_out, int out_size) {
    const float* data  = (const float*)d_in[0];
    const float* locs  = (const float*)d_in[1];
    const float* Wih   = (const float*)d_in[2];
    const float* Whh   = (const float*)d_in[3];
    const float* bih   = (const float*)d_in[4];
    const float* bhh   = (const float*)d_in[5];
    const float* Wmu   = (const float*)d_in[6];
    const float* bmu   = (const float*)d_in[7];
    const float* Wvar  = (const float*)d_in[8];
    const float* bvar  = (const float*)d_in[9];
    const float* Wvelo = (const float*)d_in[10];
    const float* bvelo = (const float*)d_in[11];
    const float* Wsw   = (const float*)d_in[12];
    const float* bsw   = (const float*)d_in[13];
    const float* Wgen  = (const float*)d_in[14];
    const float* bgen  = (const float*)d_in[15];
    const float* Won   = (const float*)d_in[16];
    const float* bon   = (const float*)d_in[17];
    const float* Wnext = (const float*)d_in[18];
    const float* bnext = (const float*)d_in[19];
    const float* Wloc  = (const float*)d_in[20];
    const float* bloc  = (const float*)d_in[21];
    const float* eps   = (const float*)d_in[22];
    float* out = (float*)d_out;

    prep_all_kernel<<<256, 512>>>(Wih, Whh, Wmu, Wvar,
                                  Wgen, bgen, Won, bon,
                                  Wvelo, bvelo, Wsw, bsw);

    // floats: 19680 (state) + 2 * 16384 (panel slots) = 52448
    const size_t smem_bytes = 52448 * sizeof(float);  // 209,792 B
    cudaFuncSetAttribute(model_kernel,
                         cudaFuncAttributeMaxDynamicSharedMemorySize,
                         (int)smem_bytes);
    model_kernel<<<NCTA, NTH, smem_bytes>>>(data, locs, bih, bhh,
                                            bmu, bvar, Wnext, bnext,
                                            Wloc, bloc, eps, out);
}